// round 6
// baseline (speedup 1.0000x reference)
#include <cuda_runtime.h>

#define BATCH 8192
#define NIN   3072
#define NOUT  512
#define EPSF  1e-20f
#define NITER 5
#define RPB   8    // batch rows per block (== warps per block)
#define T     256  // threads per block

// Dynamic smem layout: ratio[RPB*NIN] | h[RPB*NOUT] | red[RPB]
#define SMEM_BYTES ((RPB * NIN + RPB * NOUT + RPB) * (int)sizeof(float))

// One block = RPB batch rows, fully self-contained 5-iteration recurrence.
// No __device__ scratch, no inter-kernel handoff: the entire dataflow lives
// in this kernel's shared memory.
__global__ __launch_bounds__(T) void fused_nnmf_kernel(
    const float* __restrict__ x,   // [BATCH, NIN]
    const float* __restrict__ W,   // [NOUT, NIN] row-major, rows sum to 1
    const float* __restrict__ h0,  // [NOUT]
    float* __restrict__ out        // [BATCH, NOUT]
) {
    extern __shared__ float smem[];
    float* ratio = smem;                     // [RPB][NIN]
    float* h     = smem + RPB * NIN;         // [RPB][NOUT]
    float* red   = h + RPB * NOUT;           // [RPB]

    const int tid  = threadIdx.x;
    const int lane = tid & 31;
    const int warp = tid >> 5;               // 0..7 == row index within block
    const int r0   = blockIdx.x * RPB;

    // init h rows from h0 (broadcast)
    for (int i = tid; i < RPB * NOUT; i += T) h[i] = h0[i & (NOUT - 1)];

    // per-row 1/(sum(x)+eps): warp r reduces row r
    {
        const float* xr = x + (size_t)(r0 + warp) * NIN;
        float s = 0.f;
        for (int k = lane; k < NIN; k += 32) s += xr[k];
        #pragma unroll
        for (int o = 16; o; o >>= 1) s += __shfl_xor_sync(0xffffffffu, s, o);
        if (lane == 0) red[warp] = 1.0f / (s + EPSF);
    }
    __syncthreads();

    float xinv[RPB];
    #pragma unroll
    for (int r = 0; r < RPB; r++) xinv[r] = red[r];
    __syncthreads();

    for (int iter = 0; iter < NITER; iter++) {
        // ---- Phase 1: ratio[r][k] = xhat[r][k] / (sum_n h[r][n]*W[n][k] + eps)
        for (int k = tid; k < NIN; k += T) {
            float d[RPB];
            #pragma unroll
            for (int r = 0; r < RPB; r++) d[r] = 0.f;
            #pragma unroll 4
            for (int n = 0; n < NOUT; n++) {
                float w = __ldg(W + (size_t)n * NIN + k);   // coalesced
                #pragma unroll
                for (int r = 0; r < RPB; r++) d[r] += h[r * NOUT + n] * w;
            }
            #pragma unroll
            for (int r = 0; r < RPB; r++) {
                float xv = __ldg(x + (size_t)(r0 + r) * NIN + k);
                ratio[r * NIN + k] = (xv * xinv[r]) / (d[r] + EPSF);
            }
        }
        __syncthreads();

        // ---- Phase 2: t[r][n] = sum_k W[n][k]*ratio[r][k];  h = h*(1+t)
        for (int n = warp; n < NOUT; n += RPB) {
            const float* wr = W + (size_t)n * NIN;
            float t[RPB];
            #pragma unroll
            for (int r = 0; r < RPB; r++) t[r] = 0.f;
            #pragma unroll 4
            for (int k = lane; k < NIN; k += 32) {
                float w = __ldg(wr + k);                     // coalesced
                #pragma unroll
                for (int r = 0; r < RPB; r++) t[r] += ratio[r * NIN + k] * w;
            }
            #pragma unroll
            for (int r = 0; r < RPB; r++) {
                #pragma unroll
                for (int o = 16; o; o >>= 1)
                    t[r] += __shfl_xor_sync(0xffffffffu, t[r], o);
            }
            if (lane == 0) {
                #pragma unroll
                for (int r = 0; r < RPB; r++)
                    h[r * NOUT + n] = h[r * NOUT + n] * (1.0f + t[r]);
            }
        }
        __syncthreads();

        // ---- normalize h rows: warp r reduces row r
        {
            float s = 0.f;
            for (int n = lane; n < NOUT; n += 32) s += h[warp * NOUT + n];
            #pragma unroll
            for (int o = 16; o; o >>= 1) s += __shfl_xor_sync(0xffffffffu, s, o);
            if (lane == 0) red[warp] = 1.0f / (s + EPSF);
        }
        __syncthreads();
        for (int i = tid; i < RPB * NOUT; i += T) h[i] *= red[i >> 9];  // i/NOUT
        __syncthreads();
    }

    // write result
    for (int i = tid; i < RPB * NOUT; i += T)
        out[(size_t)r0 * NOUT + i] = h[i];
}

extern "C" void kernel_launch(void* const* d_in, const int* in_sizes, int n_in,
                              void* d_out, int out_size) {
    // Identify inputs by element count — immune to metadata ordering.
    const float* x = nullptr;   // BATCH*NIN = 25165824
    const float* W = nullptr;   // NOUT*NIN  = 1572864
    const float* h0 = nullptr;  // NOUT      = 512
    for (int i = 0; i < n_in; i++) {
        if (in_sizes[i] == BATCH * NIN)      x  = (const float*)d_in[i];
        else if (in_sizes[i] == NOUT * NIN)  W  = (const float*)d_in[i];
        else if (in_sizes[i] == NOUT)        h0 = (const float*)d_in[i];
    }
    float* out = (float*)d_out;  // [BATCH, NOUT]

    cudaFuncSetAttribute(fused_nnmf_kernel,
                         cudaFuncAttributeMaxDynamicSharedMemorySize, SMEM_BYTES);

    fused_nnmf_kernel<<<BATCH / RPB, T, SMEM_BYTES>>>(x, W, h0, out);
}

// round 7
// speedup vs baseline: 1.6126x; 1.6126x over previous
#include <cuda_runtime.h>
#include <cstdint>

#define BATCH 8192
#define NIN   3072
#define NOUT  512
#define EPSF  1e-20f
#define NITER 5
#define RPB   16   // batch rows per block
#define T     384  // threads (12 warps)
#define NWARP 12
#define NTILE 4    // n-rows per phase-2 pass (crossbar/fma balance)

#define SMEM_FLOATS (RPB*NIN + RPB*NOUT + 2*RPB)
#define SMEM_BYTES  (SMEM_FLOATS * 4)

// ---- Blackwell packed-fp32 helpers (FFMA2 via PTX, SASS_QUICKREF) ----------
__device__ __forceinline__ uint64_t pack2(float lo, float hi) {
    uint64_t r; asm("mov.b64 %0, {%1,%2};" : "=l"(r) : "f"(lo), "f"(hi)); return r;
}
__device__ __forceinline__ void unpack2(uint64_t v, float& lo, float& hi) {
    asm("mov.b64 {%0,%1}, %2;" : "=f"(lo), "=f"(hi) : "l"(v));
}
__device__ __forceinline__ void ffma2(uint64_t& d, uint64_t a, uint64_t b) {
    asm("fma.rn.f32x2 %0, %1, %2, %0;" : "+l"(d) : "l"(a), "l"(b));
}

// One block = RPB batch rows, fully self-contained 5-iteration recurrence in
// shared memory (single launch; the multi-kernel handoff variant was broken).
__global__ __launch_bounds__(T, 1) void fused_nnmf_kernel(
    const float* __restrict__ x,   // [BATCH, NIN]
    const float* __restrict__ W,   // [NOUT, NIN] row-major
    const float* __restrict__ h0,  // [NOUT]
    float* __restrict__ out        // [BATCH, NOUT]
) {
    extern __shared__ float smem[];
    float* ratio = smem;                 // [RPB][NIN]   192 KB
    float* h     = smem + RPB * NIN;     // [RPB][NOUT]   32 KB
    float* xinv  = h + RPB * NOUT;       // [RPB]
    float* hred  = xinv + RPB;           // [RPB]

    const int tid  = threadIdx.x;
    const int lane = tid & 31;
    const int warp = tid >> 5;
    const int r0   = blockIdx.x * RPB;

    // init h rows from h0 (broadcast)
    for (int i = tid; i < RPB * NOUT; i += T) h[i] = h0[i & (NOUT - 1)];

    // per-row 1/(sum(x)+eps)
    for (int r = warp; r < RPB; r += NWARP) {
        const float* xrp = x + (size_t)(r0 + r) * NIN;
        float s = 0.f;
        for (int k = lane; k < NIN; k += 32) s += xrp[k];
        #pragma unroll
        for (int o = 16; o; o >>= 1) s += __shfl_xor_sync(~0u, s, o);
        if (lane == 0) xinv[r] = 1.0f / (s + EPSF);
    }
    __syncthreads();

    for (int iter = 0; iter < NITER; iter++) {
        // ---- Phase 1: denom[r][k] = sum_n h[r][n]*W[n][k]; ratio = xhat/denom
        // Each thread owns 8 k-columns (2 groups of 4 consecutive).
        #pragma unroll
        for (int g = 0; g < 2; g++) {
            const int kb = g * 1536 + tid * 4;
            uint64_t d01[RPB], d23[RPB];
            #pragma unroll
            for (int r = 0; r < RPB; r++) { d01[r] = 0ull; d23[r] = 0ull; }
            const float* wp = W + kb;
            #pragma unroll 2
            for (int n = 0; n < NOUT; n++) {
                ulonglong2 w2 = *(const ulonglong2*)(wp + (size_t)n * NIN);
                #pragma unroll
                for (int r = 0; r < RPB; r++) {
                    float hv = h[r * NOUT + n];          // LDS broadcast
                    uint64_t h2 = pack2(hv, hv);
                    ffma2(d01[r], h2, w2.x);
                    ffma2(d23[r], h2, w2.y);
                }
            }
            #pragma unroll
            for (int r = 0; r < RPB; r++) {
                float4 xv = *(const float4*)(x + (size_t)(r0 + r) * NIN + kb);
                float d0, d1, d2, d3;
                unpack2(d01[r], d0, d1);
                unpack2(d23[r], d2, d3);
                float xiv = xinv[r];
                float4 o;
                o.x = __fdividef(xv.x * xiv, d0 + EPSF);
                o.y = __fdividef(xv.y * xiv, d1 + EPSF);
                o.z = __fdividef(xv.z * xiv, d2 + EPSF);
                o.w = __fdividef(xv.w * xiv, d3 + EPSF);
                *(float4*)(ratio + r * NIN + kb) = o;
            }
        }
        __syncthreads();

        // ---- Phase 2: t[r][n] = sum_k ratio[r][k]*W[n][k]; h *= (1+t)
        // Warp handles NTILE consecutive n; lanes stride k by 4 (LDG.128 /
        // LDS.128 feed FFMA2 directly as packed pairs).
        for (int n0 = warp * NTILE; n0 < NOUT; n0 += NWARP * NTILE) {
            uint64_t acc[NTILE][RPB];
            #pragma unroll
            for (int t = 0; t < NTILE; t++)
                #pragma unroll
                for (int r = 0; r < RPB; r++) acc[t][r] = 0ull;
            #pragma unroll 2
            for (int i = 0; i < NIN / 128; i++) {
                const int k = i * 128 + lane * 4;
                ulonglong2 w2[NTILE];
                #pragma unroll
                for (int t = 0; t < NTILE; t++)
                    w2[t] = *(const ulonglong2*)(W + (size_t)(n0 + t) * NIN + k);
                #pragma unroll
                for (int r = 0; r < RPB; r++) {
                    ulonglong2 rv = *(const ulonglong2*)(ratio + r * NIN + k);
                    #pragma unroll
                    for (int t = 0; t < NTILE; t++) {
                        ffma2(acc[t][r], rv.x, w2[t].x);
                        ffma2(acc[t][r], rv.y, w2[t].y);
                    }
                }
            }
            #pragma unroll
            for (int t = 0; t < NTILE; t++) {
                #pragma unroll
                for (int r = 0; r < RPB; r++) {
                    float lo, hi;
                    unpack2(acc[t][r], lo, hi);
                    float s = lo + hi;
                    #pragma unroll
                    for (int o = 16; o; o >>= 1) s += __shfl_xor_sync(~0u, s, o);
                    if (lane == 0) {
                        int idx = r * NOUT + n0 + t;
                        h[idx] = h[idx] * (1.0f + s);
                    }
                }
            }
        }
        __syncthreads();

        // ---- normalize h rows
        for (int r = warp; r < RPB; r += NWARP) {
            float s = 0.f;
            for (int n = lane; n < NOUT; n += 32) s += h[r * NOUT + n];
            #pragma unroll
            for (int o = 16; o; o >>= 1) s += __shfl_xor_sync(~0u, s, o);
            if (lane == 0) hred[r] = 1.0f / (s + EPSF);
        }
        __syncthreads();
        for (int i = tid; i < RPB * NOUT; i += T) h[i] *= hred[i >> 9];  // i/NOUT
        __syncthreads();
    }

    // write result
    for (int i = tid; i < RPB * NOUT; i += T)
        out[(size_t)r0 * NOUT + i] = h[i];
}

extern "C" void kernel_launch(void* const* d_in, const int* in_sizes, int n_in,
                              void* d_out, int out_size) {
    // Identify inputs by element count — immune to metadata ordering.
    const float* x = nullptr;   // BATCH*NIN = 25165824
    const float* W = nullptr;   // NOUT*NIN  = 1572864
    const float* h0 = nullptr;  // NOUT      = 512
    for (int i = 0; i < n_in; i++) {
        if (in_sizes[i] == BATCH * NIN)      x  = (const float*)d_in[i];
        else if (in_sizes[i] == NOUT * NIN)  W  = (const float*)d_in[i];
        else if (in_sizes[i] == NOUT)        h0 = (const float*)d_in[i];
    }
    float* out = (float*)d_out;  // [BATCH, NOUT]

    cudaFuncSetAttribute(fused_nnmf_kernel,
                         cudaFuncAttributeMaxDynamicSharedMemorySize, SMEM_BYTES);

    fused_nnmf_kernel<<<BATCH / RPB, T, SMEM_BYTES>>>(x, W, h0, out);
}

// round 8
// speedup vs baseline: 1.9208x; 1.1911x over previous
#include <cuda_runtime.h>
#include <cstdint>

#define BATCH 8192
#define NIN   3072
#define NOUT  512
#define EPSF  1e-20f
#define NITER 5
#define RPB   16   // batch rows per block
#define T     384  // threads (12 warps)
#define NWARP 12
#define NTILE 2    // n-rows per phase-2 pass (prefetch-register budget)

#define SMEM_FLOATS (RPB*NIN + RPB*NOUT + 2*RPB)
#define SMEM_BYTES  (SMEM_FLOATS * 4)

// ---- Blackwell packed-fp32 helpers (FFMA2 via PTX) -------------------------
__device__ __forceinline__ uint64_t pack2(float lo, float hi) {
    uint64_t r; asm("mov.b64 %0, {%1,%2};" : "=l"(r) : "f"(lo), "f"(hi)); return r;
}
__device__ __forceinline__ void unpack2(uint64_t v, float& lo, float& hi) {
    asm("mov.b64 {%0,%1}, %2;" : "=f"(lo), "=f"(hi) : "l"(v));
}
__device__ __forceinline__ void ffma2(uint64_t& d, uint64_t a, uint64_t b) {
    asm("fma.rn.f32x2 %0, %1, %2, %0;" : "+l"(d) : "l"(a), "l"(b));
}

// One block = RPB batch rows, fully self-contained 5-iteration recurrence in
// shared memory (single launch; multi-kernel handoff variant was broken).
__global__ __launch_bounds__(T, 1) void fused_nnmf_kernel(
    const float* __restrict__ x,   // [BATCH, NIN]
    const float* __restrict__ W,   // [NOUT, NIN] row-major
    const float* __restrict__ h0,  // [NOUT]
    float* __restrict__ out        // [BATCH, NOUT]
) {
    extern __shared__ float smem[];
    float* ratio = smem;                 // [RPB][NIN]   192 KB
    float* h     = smem + RPB * NIN;     // [RPB][NOUT]   32 KB
    float* xinv  = h + RPB * NOUT;       // [RPB]
    float* hred  = xinv + RPB;           // [RPB]

    const int tid  = threadIdx.x;
    const int lane = tid & 31;
    const int warp = tid >> 5;
    const int r0   = blockIdx.x * RPB;

    // init h rows from h0 (broadcast)
    for (int i = tid; i < RPB * NOUT; i += T) h[i] = h0[i & (NOUT - 1)];

    // per-row 1/(sum(x)+eps)
    for (int r = warp; r < RPB; r += NWARP) {
        const float* xrp = x + (size_t)(r0 + r) * NIN;
        float s = 0.f;
        for (int k = lane; k < NIN; k += 32) s += xrp[k];
        #pragma unroll
        for (int o = 16; o; o >>= 1) s += __shfl_xor_sync(~0u, s, o);
        if (lane == 0) xinv[r] = 1.0f / (s + EPSF);
    }
    __syncthreads();

    for (int iter = 0; iter < NITER; iter++) {
        // ---- Phase 1: denom[r][k] = sum_n h[r][n]*W[n][k]; ratio = xhat/denom
        // Each thread owns 8 k (2 groups of 4 consecutive). h read via LDS.128
        // (4 n per load); W software-pipelined one 4-n chunk ahead.
        #pragma unroll
        for (int g = 0; g < 2; g++) {
            const int kb = g * 1536 + tid * 4;
            uint64_t d01[RPB], d23[RPB];
            #pragma unroll
            for (int r = 0; r < RPB; r++) { d01[r] = 0ull; d23[r] = 0ull; }
            const float* wp = W + kb;

            ulonglong2 wa[4], wb[4];
            #pragma unroll
            for (int j = 0; j < 4; j++)
                wa[j] = *(const ulonglong2*)(wp + (size_t)j * NIN);

            for (int n4 = 0; n4 < NOUT; n4 += 4) {
                if (n4 + 4 < NOUT) {
                    #pragma unroll
                    for (int j = 0; j < 4; j++)
                        wb[j] = *(const ulonglong2*)(wp + (size_t)(n4 + 4 + j) * NIN);
                }
                #pragma unroll
                for (int r = 0; r < RPB; r++) {
                    float4 hv = *(const float4*)(h + r * NOUT + n4);  // LDS.128
                    uint64_t h2;
                    h2 = pack2(hv.x, hv.x); ffma2(d01[r], h2, wa[0].x); ffma2(d23[r], h2, wa[0].y);
                    h2 = pack2(hv.y, hv.y); ffma2(d01[r], h2, wa[1].x); ffma2(d23[r], h2, wa[1].y);
                    h2 = pack2(hv.z, hv.z); ffma2(d01[r], h2, wa[2].x); ffma2(d23[r], h2, wa[2].y);
                    h2 = pack2(hv.w, hv.w); ffma2(d01[r], h2, wa[3].x); ffma2(d23[r], h2, wa[3].y);
                }
                #pragma unroll
                for (int j = 0; j < 4; j++) wa[j] = wb[j];
            }

            #pragma unroll
            for (int r = 0; r < RPB; r++) {
                float4 xv = *(const float4*)(x + (size_t)(r0 + r) * NIN + kb);
                float d0, d1, d2, d3;
                unpack2(d01[r], d0, d1);
                unpack2(d23[r], d2, d3);
                float xiv = xinv[r];
                float4 o;
                o.x = __fdividef(xv.x * xiv, d0 + EPSF);
                o.y = __fdividef(xv.y * xiv, d1 + EPSF);
                o.z = __fdividef(xv.z * xiv, d2 + EPSF);
                o.w = __fdividef(xv.w * xiv, d3 + EPSF);
                *(float4*)(ratio + r * NIN + kb) = o;
            }
        }
        __syncthreads();

        // ---- Phase 2: t[r][n] = sum_k ratio[r][k]*W[n][k]; h *= (1+t)
        // Warp handles NTILE=2 n per pass; W double-buffered across the k-loop.
        for (int n0 = warp * NTILE; n0 < NOUT; n0 += NWARP * NTILE) {
            uint64_t acc0[RPB], acc1[RPB];
            #pragma unroll
            for (int r = 0; r < RPB; r++) { acc0[r] = 0ull; acc1[r] = 0ull; }
            const float* w0 = W + (size_t)n0 * NIN;
            const float* w1 = W + (size_t)(n0 + 1) * NIN;

            ulonglong2 wa0 = *(const ulonglong2*)(w0 + lane * 4);
            ulonglong2 wa1 = *(const ulonglong2*)(w1 + lane * 4);
            ulonglong2 wb0, wb1;

            for (int i = 0; i < NIN / 128; i++) {
                if (i + 1 < NIN / 128) {
                    const int kn = (i + 1) * 128 + lane * 4;
                    wb0 = *(const ulonglong2*)(w0 + kn);
                    wb1 = *(const ulonglong2*)(w1 + kn);
                }
                const int kk = i * 128 + lane * 4;
                #pragma unroll
                for (int r = 0; r < RPB; r++) {
                    ulonglong2 rv = *(const ulonglong2*)(ratio + r * NIN + kk);
                    ffma2(acc0[r], rv.x, wa0.x); ffma2(acc0[r], rv.y, wa0.y);
                    ffma2(acc1[r], rv.x, wa1.x); ffma2(acc1[r], rv.y, wa1.y);
                }
                wa0 = wb0; wa1 = wb1;
            }

            #pragma unroll
            for (int r = 0; r < RPB; r++) {
                float lo, hi;
                unpack2(acc0[r], lo, hi);
                float s0 = lo + hi;
                unpack2(acc1[r], lo, hi);
                float s1 = lo + hi;
                #pragma unroll
                for (int o = 16; o; o >>= 1) {
                    s0 += __shfl_xor_sync(~0u, s0, o);
                    s1 += __shfl_xor_sync(~0u, s1, o);
                }
                if (lane == 0) {
                    int i0 = r * NOUT + n0;
                    h[i0]     = h[i0]     * (1.0f + s0);
                    h[i0 + 1] = h[i0 + 1] * (1.0f + s1);
                }
            }
        }
        __syncthreads();

        // ---- normalize h rows
        for (int r = warp; r < RPB; r += NWARP) {
            float s = 0.f;
            for (int n = lane; n < NOUT; n += 32) s += h[r * NOUT + n];
            #pragma unroll
            for (int o = 16; o; o >>= 1) s += __shfl_xor_sync(~0u, s, o);
            if (lane == 0) hred[r] = 1.0f / (s + EPSF);
        }
        __syncthreads();
        for (int i = tid; i < RPB * NOUT; i += T) h[i] *= hred[i >> 9];  // i/NOUT
        __syncthreads();
    }

    // write result
    for (int i = tid; i < RPB * NOUT; i += T)
        out[(size_t)r0 * NOUT + i] = h[i];
}

extern "C" void kernel_launch(void* const* d_in, const int* in_sizes, int n_in,
                              void* d_out, int out_size) {
    // Identify inputs by element count — immune to metadata ordering.
    const float* x = nullptr;   // BATCH*NIN = 25165824
    const float* W = nullptr;   // NOUT*NIN  = 1572864
    const float* h0 = nullptr;  // NOUT      = 512
    for (int i = 0; i < n_in; i++) {
        if (in_sizes[i] == BATCH * NIN)      x  = (const float*)d_in[i];
        else if (in_sizes[i] == NOUT * NIN)  W  = (const float*)d_in[i];
        else if (in_sizes[i] == NOUT)        h0 = (const float*)d_in[i];
    }
    float* out = (float*)d_out;  // [BATCH, NOUT]

    cudaFuncSetAttribute(fused_nnmf_kernel,
                         cudaFuncAttributeMaxDynamicSharedMemorySize, SMEM_BYTES);

    fused_nnmf_kernel<<<BATCH / RPB, T, SMEM_BYTES>>>(x, W, h0, out);
}

// round 9
// speedup vs baseline: 2.7116x; 1.4117x over previous
#include <cuda_runtime.h>
#include <cstdint>

#define BATCH 8192
#define NIN   3072
#define NOUT  512
#define EPSF  1e-20f
#define NITER 5
#define RPB   8    // batch rows per block (halved: 2 blocks/SM)
#define T     256  // threads (8 warps)
#define NWARP 8
#define NTILE 4    // n-rows per phase-2 pass (crossbar << fma by design)

#define SMEM_FLOATS (RPB*NIN + RPB*NOUT + 2*RPB)
#define SMEM_BYTES  (SMEM_FLOATS * 4)   // 112.3 KB -> 2 blocks/SM

// ---- Blackwell packed-fp32 helpers (FFMA2 via PTX) -------------------------
__device__ __forceinline__ uint64_t pack2(float lo, float hi) {
    uint64_t r; asm("mov.b64 %0, {%1,%2};" : "=l"(r) : "f"(lo), "f"(hi)); return r;
}
__device__ __forceinline__ void unpack2(uint64_t v, float& lo, float& hi) {
    asm("mov.b64 {%0,%1}, %2;" : "=f"(lo), "=f"(hi) : "l"(v));
}
__device__ __forceinline__ void ffma2(uint64_t& d, uint64_t a, uint64_t b) {
    asm("fma.rn.f32x2 %0, %1, %2, %0;" : "+l"(d) : "l"(a), "l"(b));
}

// One block = RPB batch rows, fully self-contained 5-iteration recurrence in
// shared memory (single launch; multi-kernel handoff variant was broken).
__global__ __launch_bounds__(T, 2) void fused_nnmf_kernel(
    const float* __restrict__ x,   // [BATCH, NIN]
    const float* __restrict__ W,   // [NOUT, NIN] row-major
    const float* __restrict__ h0,  // [NOUT]
    float* __restrict__ out        // [BATCH, NOUT]
) {
    extern __shared__ float smem[];
    float* ratio = smem;                 // [RPB][NIN]   96 KB
    float* h     = smem + RPB * NIN;     // [RPB][NOUT]  16 KB
    float* xinv  = h + RPB * NOUT;       // [RPB]
    float* hred  = xinv + RPB;           // [RPB]

    const int tid  = threadIdx.x;
    const int lane = tid & 31;
    const int warp = tid >> 5;
    const int r0   = blockIdx.x * RPB;

    // init h rows from h0 (broadcast)
    for (int i = tid; i < RPB * NOUT; i += T) h[i] = h0[i & (NOUT - 1)];

    // per-row 1/(sum(x)+eps)
    for (int r = warp; r < RPB; r += NWARP) {
        const float* xrp = x + (size_t)(r0 + r) * NIN;
        float s = 0.f;
        for (int k = lane; k < NIN; k += 32) s += xrp[k];
        #pragma unroll
        for (int o = 16; o; o >>= 1) s += __shfl_xor_sync(~0u, s, o);
        if (lane == 0) xinv[r] = 1.0f / (s + EPSF);
    }
    __syncthreads();

    for (int iter = 0; iter < NITER; iter++) {
        // ---- Phase 1: denom[r][k] = sum_n h[r][n]*W[n][k]; ratio = xhat/denom
        // Each thread owns 12 k (3 groups of 4 consecutive). h via LDS.128
        // broadcast (4 n per load); W software-pipelined one 4-n chunk ahead.
        #pragma unroll
        for (int g = 0; g < 3; g++) {
            const int kb = g * 1024 + tid * 4;
            uint64_t d01[RPB], d23[RPB];
            #pragma unroll
            for (int r = 0; r < RPB; r++) { d01[r] = 0ull; d23[r] = 0ull; }
            const float* wp = W + kb;

            ulonglong2 wa[4], wb[4];
            #pragma unroll
            for (int j = 0; j < 4; j++)
                wa[j] = *(const ulonglong2*)(wp + (size_t)j * NIN);

            for (int n4 = 0; n4 < NOUT; n4 += 4) {
                if (n4 + 4 < NOUT) {
                    #pragma unroll
                    for (int j = 0; j < 4; j++)
                        wb[j] = *(const ulonglong2*)(wp + (size_t)(n4 + 4 + j) * NIN);
                }
                #pragma unroll
                for (int r = 0; r < RPB; r++) {
                    float4 hv = *(const float4*)(h + r * NOUT + n4);  // LDS.128 bcast
                    uint64_t h2;
                    h2 = pack2(hv.x, hv.x); ffma2(d01[r], h2, wa[0].x); ffma2(d23[r], h2, wa[0].y);
                    h2 = pack2(hv.y, hv.y); ffma2(d01[r], h2, wa[1].x); ffma2(d23[r], h2, wa[1].y);
                    h2 = pack2(hv.z, hv.z); ffma2(d01[r], h2, wa[2].x); ffma2(d23[r], h2, wa[2].y);
                    h2 = pack2(hv.w, hv.w); ffma2(d01[r], h2, wa[3].x); ffma2(d23[r], h2, wa[3].y);
                }
                #pragma unroll
                for (int j = 0; j < 4; j++) wa[j] = wb[j];
            }

            #pragma unroll
            for (int r = 0; r < RPB; r++) {
                float4 xv = *(const float4*)(x + (size_t)(r0 + r) * NIN + kb);
                float d0, d1, d2, d3;
                unpack2(d01[r], d0, d1);
                unpack2(d23[r], d2, d3);
                float xiv = xinv[r];
                float4 o;
                o.x = __fdividef(xv.x * xiv, d0 + EPSF);
                o.y = __fdividef(xv.y * xiv, d1 + EPSF);
                o.z = __fdividef(xv.z * xiv, d2 + EPSF);
                o.w = __fdividef(xv.w * xiv, d3 + EPSF);
                *(float4*)(ratio + r * NIN + kb) = o;
            }
        }
        __syncthreads();

        // ---- Phase 2: t[r][n] = sum_k ratio[r][k]*W[n][k]; h *= (1+t)
        // Warp handles NTILE=4 n per pass; each ratio LDS.128 feeds 8 FFMA2.
        for (int n0 = warp * NTILE; n0 < NOUT; n0 += NWARP * NTILE) {
            uint64_t acc[NTILE][RPB];
            #pragma unroll
            for (int t = 0; t < NTILE; t++)
                #pragma unroll
                for (int r = 0; r < RPB; r++) acc[t][r] = 0ull;

            #pragma unroll 2
            for (int i = 0; i < NIN / 128; i++) {
                const int kk = i * 128 + lane * 4;
                ulonglong2 w2[NTILE];
                #pragma unroll
                for (int t = 0; t < NTILE; t++)
                    w2[t] = *(const ulonglong2*)(W + (size_t)(n0 + t) * NIN + kk);
                #pragma unroll
                for (int r = 0; r < RPB; r++) {
                    ulonglong2 rv = *(const ulonglong2*)(ratio + r * NIN + kk);
                    #pragma unroll
                    for (int t = 0; t < NTILE; t++) {
                        ffma2(acc[t][r], rv.x, w2[t].x);
                        ffma2(acc[t][r], rv.y, w2[t].y);
                    }
                }
            }

            #pragma unroll
            for (int t = 0; t < NTILE; t++) {
                #pragma unroll
                for (int r = 0; r < RPB; r++) {
                    float lo, hi;
                    unpack2(acc[t][r], lo, hi);
                    float s = lo + hi;
                    #pragma unroll
                    for (int o = 16; o; o >>= 1) s += __shfl_xor_sync(~0u, s, o);
                    if (lane == 0) {
                        int idx = r * NOUT + n0 + t;
                        h[idx] = h[idx] * (1.0f + s);
                    }
                }
            }
        }
        __syncthreads();

        // ---- normalize h rows
        for (int r = warp; r < RPB; r += NWARP) {
            float s = 0.f;
            for (int n = lane; n < NOUT; n += 32) s += h[r * NOUT + n];
            #pragma unroll
            for (int o = 16; o; o >>= 1) s += __shfl_xor_sync(~0u, s, o);
            if (lane == 0) hred[r] = 1.0f / (s + EPSF);
        }
        __syncthreads();
        for (int i = tid; i < RPB * NOUT; i += T) h[i] *= hred[i >> 9];  // i/NOUT
        __syncthreads();
    }

    // write result
    for (int i = tid; i < RPB * NOUT; i += T)
        out[(size_t)r0 * NOUT + i] = h[i];
}

extern "C" void kernel_launch(void* const* d_in, const int* in_sizes, int n_in,
                              void* d_out, int out_size) {
    // Identify inputs by element count — immune to metadata ordering.
    const float* x = nullptr;   // BATCH*NIN = 25165824
    const float* W = nullptr;   // NOUT*NIN  = 1572864
    const float* h0 = nullptr;  // NOUT      = 512
    for (int i = 0; i < n_in; i++) {
        if (in_sizes[i] == BATCH * NIN)      x  = (const float*)d_in[i];
        else if (in_sizes[i] == NOUT * NIN)  W  = (const float*)d_in[i];
        else if (in_sizes[i] == NOUT)        h0 = (const float*)d_in[i];
    }
    float* out = (float*)d_out;  // [BATCH, NOUT]

    cudaFuncSetAttribute(fused_nnmf_kernel,
                         cudaFuncAttributeMaxDynamicSharedMemorySize, SMEM_BYTES);

    fused_nnmf_kernel<<<BATCH / RPB, T, SMEM_BYTES>>>(x, W, h0, out);
}